// round 8
// baseline (speedup 1.0000x reference)
#include <cuda_runtime.h>
#include <cuda_bf16.h>
#include <cstdint>

// VQ on GB300 via legacy mma.sync: single-pass bf16 distance-GEMM with
// DEPTH-1 accumulator chains (sm_103 legacy-MMA RAW latency ~650cyc made
// chained accumulation the R4-R7 bottleneck), packed top-4 argmin,
// rigorous per-row error bound, inline 3-candidate exact resolve,
// full exact rescan only for ~0.4% of rows.

#define NROWS  131072
#define CDIM   64
#define NE     1024
#define MT     128              // rows per CTA
#define TPB    256              // 8 warps x 16 rows
#define NBLK   (NROWS/MT)       // 1024
#define NCHUNK 8                // 8 chunks x 128 codes

typedef unsigned int u32;

__device__ unsigned char g_Bhi[NE * CDIM * 2];   // [chunk128][code][k] bf16, SW128
__device__ float  g_e2[NE];
__device__ int    g_e2maxbits = 0;   // max ||e||^2 bits (idempotent across replays)
__device__ double g_loss_acc;
__device__ int    g_fb_cnt;
__device__ int    g_fb_rows[NROWS];

#define SW128(x) ((x) ^ (((x) >> 3) & 0x70))

__device__ __forceinline__ u32 smaddr(const void* p) {
    u32 a;
    asm("{ .reg .u64 t; cvta.to.shared.u64 t, %1; cvt.u32.u64 %0, t; }" : "=r"(a) : "l"(p));
    return a;
}
__device__ __forceinline__ void cpa16(u32 sd, const void* src) {
    asm volatile("cp.async.cg.shared.global [%0], [%1], 16;" :: "r"(sd), "l"(src));
}
#define CPA_COMMIT() asm volatile("cp.async.commit_group;")
#define CPA_WAIT0()  asm volatile("cp.async.wait_group 0;" ::: "memory")
#define CPA_WAIT1()  asm volatile("cp.async.wait_group 1;" ::: "memory")

__device__ __forceinline__ void ldsm4(u32* r, u32 addr) {
    asm volatile("ldmatrix.sync.aligned.m8n8.x4.shared.b16 {%0,%1,%2,%3}, [%4];"
                 : "=r"(r[0]), "=r"(r[1]), "=r"(r[2]), "=r"(r[3]) : "r"(addr));
}
__device__ __forceinline__ void mma16816(float* c, const u32* a, const u32* b) {
    asm volatile("mma.sync.aligned.m16n8k16.row.col.f32.bf16.bf16.f32 "
                 "{%0,%1,%2,%3}, {%4,%5,%6,%7}, {%8,%9}, {%0,%1,%2,%3};"
                 : "+f"(c[0]), "+f"(c[1]), "+f"(c[2]), "+f"(c[3])
                 : "r"(a[0]), "r"(a[1]), "r"(a[2]), "r"(a[3]), "r"(b[0]), "r"(b[1]));
}
__device__ __forceinline__ u32 bits2(__nv_bfloat162 h) { return *reinterpret_cast<u32*>(&h); }

// sorted insert into ascending (m[0..3])
__device__ __forceinline__ void ins4(float* m, float q) {
    float t1 = fmaxf(m[0], q); m[0] = fminf(m[0], q);
    float t2 = fmaxf(m[1], t1); m[1] = fminf(m[1], t1);
    float t3 = fmaxf(m[2], t2); m[2] = fminf(m[2], t2);
    m[3] = fminf(m[3], t3);
}

// ---- prep: codebook bf16 + SW128 swizzle per 128-code chunk + norms ----
__global__ void vq_prep_e(const float* __restrict__ embs) {
    int t = blockIdx.x * 256 + threadIdx.x;   // 8192 = 1024 codes x 8 k-chunks
    int c = t >> 3, kc = t & 7;
    const float4* s = (const float4*)(embs + (size_t)c * CDIM + kc * 8);
    float4 a = s[0], b = s[1];
    u32 hi[4];
    hi[0] = bits2(__floats2bfloat162_rn(a.x, a.y));
    hi[1] = bits2(__floats2bfloat162_rn(a.z, a.w));
    hi[2] = bits2(__floats2bfloat162_rn(b.x, b.y));
    hi[3] = bits2(__floats2bfloat162_rn(b.z, b.w));
    size_t off = (size_t)(c >> 7) * 16384 + SW128((c & 127) * 128 + kc * 16);
    *(uint4*)(g_Bhi + off) = make_uint4(hi[0], hi[1], hi[2], hi[3]);
    if (kc == 0) {
        const float4* p = (const float4*)(embs + (size_t)c * CDIM);
        float e2 = 0.f;
        #pragma unroll
        for (int q = 0; q < 16; q++) {
            float4 v = p[q];
            e2 += v.x * v.x + v.y * v.y + v.z * v.z + v.w * v.w;
        }
        g_e2[c] = e2;
        atomicMax(&g_e2maxbits, __float_as_int(e2));
    }
    if (t == 0) { g_loss_acc = 0.0; g_fb_cnt = 0; }
}

// ---- smem layout ----
#define SM_E2   0                 // 4KB  e2[1024]
#define SM_RED  4096              // 32B
#define SM_B    8192              // 2 x 16KB double-buffered B chunks
#define SMEM_SZ (8192 + 32768)

__global__ __launch_bounds__(TPB, 3) void vq_main(
    const float* __restrict__ ze, const float* __restrict__ embs,
    float* __restrict__ out)
{
    extern __shared__ unsigned char sm[];
    const u32 sb  = smaddr(sm);
    const int tid = threadIdx.x;
    const int w   = tid >> 5;
    const int ln  = tid & 31;
    const size_t row0 = (size_t)blockIdx.x * MT;

    // prologue: e2 + chunk0 (group 0), chunk1 (group 1)
    cpa16(sb + SM_E2 + tid * 16, (const unsigned char*)g_e2 + tid * 16);
    #pragma unroll
    for (int i = 0; i < 4; i++)
        cpa16(sb + SM_B + i * 4096 + tid * 16, g_Bhi + i * 4096 + tid * 16);
    CPA_COMMIT();
    #pragma unroll
    for (int i = 0; i < 4; i++)
        cpa16(sb + SM_B + 16384 + i * 4096 + tid * 16, g_Bhi + 16384 + i * 4096 + tid * 16);
    CPA_COMMIT();

    // A fragments: 16 rows, K=64, bf16 single-pass -> 16 regs; + row norms
    u32 Ahi[4][4];
    float zn2a = 0.f, zn2b = 0.f;     // ||z||^2 for rows ln>>2 and ln>>2+8
    {
        const float2* zp = (const float2*)ze;
        const size_t rA = row0 + w * 16 + (ln >> 2);
        #pragma unroll
        for (int ks = 0; ks < 4; ks++) {
            int kp = ks * 8 + (ln & 3);
            float2 v0 = zp[rA * 32 + kp];
            float2 v1 = zp[(rA + 8) * 32 + kp];
            float2 v2 = zp[rA * 32 + kp + 4];
            float2 v3 = zp[(rA + 8) * 32 + kp + 4];
            Ahi[ks][0] = bits2(__floats2bfloat162_rn(v0.x, v0.y));
            Ahi[ks][1] = bits2(__floats2bfloat162_rn(v1.x, v1.y));
            Ahi[ks][2] = bits2(__floats2bfloat162_rn(v2.x, v2.y));
            Ahi[ks][3] = bits2(__floats2bfloat162_rn(v3.x, v3.y));
            zn2a += v0.x * v0.x + v0.y * v0.y + v2.x * v2.x + v2.y * v2.y;
            zn2b += v1.x * v1.x + v1.y * v1.y + v3.x * v3.x + v3.y * v3.y;
        }
        zn2a += __shfl_xor_sync(0xffffffffu, zn2a, 1);
        zn2a += __shfl_xor_sync(0xffffffffu, zn2a, 2);
        zn2b += __shfl_xor_sync(0xffffffffu, zn2b, 1);
        zn2b += __shfl_xor_sync(0xffffffffu, zn2b, 2);
    }

    const u32 lane0 = SW128((u32)((ln & 7) * 128 + 16 * (ln >> 3)));
    const u32 lane1 = SW128((u32)((ln & 7) * 128 + 16 * (ln >> 3) + 64));

    float m[2][4];                    // packed ascending top-4 per s-half
    #pragma unroll
    for (int s = 0; s < 2; s++)
        #pragma unroll
        for (int j = 0; j < 4; j++) m[s][j] = 3.4e38f;

    const float* e2s = (const float*)(sm + SM_E2);

    for (int t = 0; t < NCHUNK; t++) {
        const int b = t & 1;
        if (t < NCHUNK - 1) CPA_WAIT1(); else CPA_WAIT0();
        __syncthreads();

        const u32 bhi = sb + SM_B + b * 16384;

        #pragma unroll 4
        for (int nt = 0; nt < 16; nt++) {
            const int nl = nt * 8;
            u32 bh[8];
            ldsm4(bh,     bhi + nl * 128 + lane0);
            ldsm4(bh + 4, bhi + nl * 128 + lane1);

            // 4 INDEPENDENT depth-1 MMA chains (per ks)
            float acc[4][4];
            #pragma unroll
            for (int ks = 0; ks < 4; ks++) {
                #pragma unroll
                for (int j = 0; j < 4; j++) acc[ks][j] = 0.f;
                mma16816(acc[ks], Ahi[ks], &bh[ks * 2]);
            }
            float c4[4];
            #pragma unroll
            for (int j = 0; j < 4; j++)
                c4[j] = (acc[0][j] + acc[1][j]) + (acc[2][j] + acc[3][j]);

            const int c0 = t * 128 + nl + 2 * (ln & 3);
            float2 e2v = *(const float2*)(e2s + c0);
            #pragma unroll
            for (int s = 0; s < 2; s++) {
                float d0 = fmaf(c4[s * 2],     -2.f, e2v.x);
                float d1 = fmaf(c4[s * 2 + 1], -2.f, e2v.y);
                float q0 = __uint_as_float((__float_as_uint(d0) & 0xFFFFFC00u) | (u32)c0);
                float q1 = __uint_as_float((__float_as_uint(d1) & 0xFFFFFC00u) | (u32)(c0 + 1));
                ins4(m[s], q0);
                ins4(m[s], q1);
            }
        }
        __syncthreads();
        if (t + 2 < NCHUNK) {
            const u32 d = sb + SM_B + b * 16384;
            const size_t goff = (size_t)(t + 2) * 16384;
            #pragma unroll
            for (int i = 0; i < 4; i++)
                cpa16(d + i * 4096 + tid * 16, g_Bhi + goff + i * 4096 + tid * 16);
            CPA_COMMIT();
        }
    }

    // merge top-4 across the 4 lanes of each quad
    #pragma unroll
    for (int s = 0; s < 2; s++) {
        #pragma unroll
        for (int d = 1; d <= 2; d <<= 1) {
            float o0 = __shfl_xor_sync(0xffffffffu, m[s][0], d);
            float o1 = __shfl_xor_sync(0xffffffffu, m[s][1], d);
            float o2 = __shfl_xor_sync(0xffffffffu, m[s][2], d);
            float o3 = __shfl_xor_sync(0xffffffffu, m[s][3], d);
            ins4(m[s], o0); ins4(m[s], o1); ins4(m[s], o2); ins4(m[s], o3);
        }
    }

    const float nemax = sqrtf(__int_as_float(g_e2maxbits));
    float ls = 0.f;
    #pragma unroll 1
    for (int r = 0; r < 16; r++) {
        const int src = (r & 7) * 4;
        float f1a = __shfl_sync(0xffffffffu, m[0][0], src), f1b = __shfl_sync(0xffffffffu, m[1][0], src);
        float f2a = __shfl_sync(0xffffffffu, m[0][1], src), f2b = __shfl_sync(0xffffffffu, m[1][1], src);
        float f3a = __shfl_sync(0xffffffffu, m[0][2], src), f3b = __shfl_sync(0xffffffffu, m[1][2], src);
        float f4a = __shfl_sync(0xffffffffu, m[0][3], src), f4b = __shfl_sync(0xffffffffu, m[1][3], src);
        float za  = __shfl_sync(0xffffffffu, zn2a, src),    zb  = __shfl_sync(0xffffffffu, zn2b, src);
        float f1 = (r < 8) ? f1a : f1b;
        float f2 = (r < 8) ? f2a : f2b;
        float f3 = (r < 8) ? f3a : f3b;
        float f4 = (r < 8) ? f4a : f4b;
        float zn2r = (r < 8) ? za : zb;
        const float TH = fmaf(0.035f * sqrtf(zn2r), nemax, 0.10f);
        const size_t grow = row0 + w * 16 + r;
        int code;

        if (f2 - f1 >= TH) {
            code = (int)(__float_as_uint(f1) & 0x3FFu);        // provable winner
        } else if (f4 - f1 >= TH) {
            // winner provably in top-3: exact fp32 resolve on lanes 0..2
            int ci = (int)(__float_as_uint(ln == 0 ? f1 : (ln == 1 ? f2 : f3)) & 0x3FFu);
            float d = 3.4e38f;
            if (ln < 3) {
                const float4* z4 = (const float4*)(ze + grow * CDIM);
                const float4* e4 = (const float4*)(embs + (size_t)ci * CDIM);
                float zn = 0.f, dt = 0.f;
                #pragma unroll
                for (int q = 0; q < 16; q++) {
                    float4 zr = z4[q], e = e4[q];
                    zn += zr.x * zr.x + zr.y * zr.y + zr.z * zr.z + zr.w * zr.w;
                    dt = fmaf(e.x, zr.x, dt); dt = fmaf(e.y, zr.y, dt);
                    dt = fmaf(e.z, zr.z, dt); dt = fmaf(e.w, zr.w, dt);
                }
                d = fmaf(dt, -2.f, zn + e2s[ci]);
            }
            #pragma unroll
            for (int off = 2; off > 0; off >>= 1) {
                float od = __shfl_down_sync(0xffffffffu, d, off);
                int   oc = __shfl_down_sync(0xffffffffu, ci, off);
                if (od < d || (od == d && oc < ci)) { d = od; ci = oc; }
            }
            code = __shfl_sync(0xffffffffu, ci, 0);
        } else {
            if (ln == 0) { int p = atomicAdd(&g_fb_cnt, 1); g_fb_rows[p] = (int)grow; }
            continue;                                          // rare full rescan
        }

        float2 e = ((const float2*)(embs + (size_t)code * CDIM))[ln];
        float2 z = ((const float2*)(ze + grow * CDIM))[ln];
        ((float2*)(out + grow * CDIM))[ln] = e;
        float d0 = e.x - z.x, d1 = e.y - z.y;
        ls += d0 * d0 + d1 * d1;
    }
    #pragma unroll
    for (int off = 16; off > 0; off >>= 1)
        ls += __shfl_down_sync(0xffffffffu, ls, off);
    float* sred = (float*)(sm + SM_RED);
    if (ln == 0) sred[w] = ls;
    __syncthreads();
    if (tid == 0) {
        float s = 0.f;
        #pragma unroll
        for (int i = 0; i < 8; i++) s += sred[i];
        atomicAdd(&g_loss_acc, (double)s);
    }
}

// ---- exact fp32 full rescan (rare rows) ----
__global__ void vq_fb(const float* __restrict__ ze, const float* __restrict__ embs,
                      float* __restrict__ out)
{
    const int n  = g_fb_cnt;
    const int wg = (blockIdx.x * blockDim.x + threadIdx.x) >> 5;
    const int ln = threadIdx.x & 31;
    const int nw = (gridDim.x * blockDim.x) >> 5;

    for (int i = wg; i < n; i += nw) {
        const int row = g_fb_rows[i];
        const float4* z4 = (const float4*)(ze + (size_t)row * CDIM);
        float4 zr[16];
        float zn = 0.f;
        #pragma unroll
        for (int q = 0; q < 16; q++) {
            zr[q] = z4[q];
            zn += zr[q].x * zr[q].x + zr[q].y * zr[q].y + zr[q].z * zr[q].z + zr[q].w * zr[q].w;
        }
        float best = 3.4e38f; int bi = 1 << 30;
        for (int c = ln; c < NE; c += 32) {
            const float4* e4 = (const float4*)(embs + (size_t)c * CDIM);
            float dt = 0.f;
            #pragma unroll
            for (int q = 0; q < 16; q++) {
                float4 e = e4[q];
                dt = fmaf(e.x, zr[q].x, dt); dt = fmaf(e.y, zr[q].y, dt);
                dt = fmaf(e.z, zr[q].z, dt); dt = fmaf(e.w, zr[q].w, dt);
            }
            float dist = fmaf(dt, -2.f, zn + g_e2[c]);
            if (dist < best) { best = dist; bi = c; }
        }
        #pragma unroll
        for (int off = 16; off > 0; off >>= 1) {
            float ob = __shfl_down_sync(0xffffffffu, best, off);
            int   oi = __shfl_down_sync(0xffffffffu, bi, off);
            if (ob < best || (ob == best && oi < bi)) { best = ob; bi = oi; }
        }
        bi = __shfl_sync(0xffffffffu, bi, 0);

        float2 ev = ((const float2*)(embs + (size_t)bi * CDIM))[ln];
        float2 zv = ((const float2*)(ze + (size_t)row * CDIM))[ln];
        ((float2*)(out + (size_t)row * CDIM))[ln] = ev;
        float d0 = ev.x - zv.x, d1 = ev.y - zv.y;
        float ls = d0 * d0 + d1 * d1;
        #pragma unroll
        for (int off = 16; off > 0; off >>= 1)
            ls += __shfl_down_sync(0xffffffffu, ls, off);
        if (ln == 0) atomicAdd(&g_loss_acc, (double)ls);
    }
}

__global__ void vq_fin(float* loss_out) {
    *loss_out = (float)(1.25 * g_loss_acc / (double)((long long)NROWS * CDIM));
}

extern "C" void kernel_launch(void* const* d_in, const int* in_sizes, int n_in,
                              void* d_out, int out_size) {
    const float* ze   = (const float*)d_in[0];
    const float* embs = (const float*)d_in[1];
    float* out = (float*)d_out;

    cudaFuncSetAttribute(vq_main, cudaFuncAttributeMaxDynamicSharedMemorySize, SMEM_SZ);

    vq_prep_e<<<NE * 8 / 256, 256>>>(embs);
    vq_main<<<NBLK, TPB, SMEM_SZ>>>(ze, embs, out);
    vq_fb<<<128, 256>>>(ze, embs, out);
    if (out_size > NROWS * CDIM)
        vq_fin<<<1, 1>>>(out + (out_size - 1));
}

// round 9
// speedup vs baseline: 2.6131x; 2.6131x over previous
#include <cuda_runtime.h>
#include <cstdint>

// VQ on GB300 — SIMT f32x2 path (R2 scaled up): fused distance-GEMM + argmin.
// TPB 256 (4 warps/SMSP), 128-row tiles, 128-code smem chunks (single-buffered,
// refill overlapped with distance finalize), exact fp32 numerics (R2 op order).

#define NROWS  131072
#define CDIM   64
#define NE     1024
#define TPB    256
#define RPB    128                 // rows per block
#define NBLK   (NROWS/RPB)         // 1024
#define CH     128                 // codes per smem chunk
#define NCH    (NE/CH)             // 8

typedef unsigned long long ull;

__device__ ull    g_eTd[CDIM * NE];  // [k][c] -> {e,e}  (512KB)
__device__ ull    g_e2d[NE];         // {||e||^2, ||e||^2}
__device__ double g_loss_acc;

__device__ __forceinline__ ull pk2(float lo, float hi) {
    ull d; asm("mov.b64 %0, {%1, %2};" : "=l"(d) : "f"(lo), "f"(hi)); return d;
}
__device__ __forceinline__ void upk2(ull v, float& lo, float& hi) {
    asm("mov.b64 {%0, %1}, %2;" : "=f"(lo), "=f"(hi) : "l"(v));
}
__device__ __forceinline__ ull ffma2(ull a, ull b, ull c) {
    ull d; asm("fma.rn.f32x2 %0, %1, %2, %3;" : "=l"(d) : "l"(a), "l"(b), "l"(c)); return d;
}
__device__ __forceinline__ ull add2(ull a, ull b) {
    ull d; asm("add.rn.f32x2 %0, %1, %2;" : "=l"(d) : "l"(a), "l"(b)); return d;
}
__device__ __forceinline__ void cpa16(void* dst, const void* src) {
    unsigned sd = (unsigned)__cvta_generic_to_shared(dst);
    asm volatile("cp.async.cg.shared.global [%0], [%1], 16;" :: "r"(sd), "l"(src));
}
#define CPA_COMMIT() asm volatile("cp.async.commit_group;")
#define CPA_WAIT0()  asm volatile("cp.async.wait_group 0;" ::: "memory")

// Prologue 1: transpose + duplicate codebook into g_eTd; zero loss acc.
__global__ void vq_prep(const float* __restrict__ embs) {
    int idx = blockIdx.x * 256 + threadIdx.x;      // = c*64 + k (coalesced read)
    if (idx == 0) g_loss_acc = 0.0;
    float v = embs[idx];
    int c = idx >> 6, k = idx & 63;
    g_eTd[k * NE + c] = pk2(v, v);
}

// Prologue 2: per-code squared norms (duplicated).
__global__ void vq_prep2(const float* __restrict__ embs) {
    int c = blockIdx.x * 128 + threadIdx.x;
    const float4* p = (const float4*)(embs + (size_t)c * CDIM);
    float s = 0.f;
    #pragma unroll
    for (int q = 0; q < 16; q++) {
        float4 v = p[q];
        s += v.x * v.x + v.y * v.y + v.z * v.z + v.w * v.w;
    }
    g_e2d[c] = pk2(s, s);
}

// smem layout (ull units):
//  sED  [64][128] : 8192 ull   e chunk (dup), single buffer; reused in epilogue
//  zT   [64][64]  : 4096 ull   zT[k][p] = {z[2p][k], z[2p+1][k]}
//  sE2  [1024]    : 1024 ull   all code norms (dup)
//  sznf [128] f   :   64 ull
//  sidx [128] i   :   64 ull
//  sred [8] f     :    8 ull
#define SMEM_ULL  (8192 + 4096 + 1024 + 64 + 64 + 8)
#define SMEM_B    (SMEM_ULL * 8)

__global__ __launch_bounds__(TPB, 2) void vq_main(
    const float* __restrict__ ze, const float* __restrict__ embs,
    float* __restrict__ out)
{
    extern __shared__ ull sm[];
    ull*   sED  = sm;                         // [64][128]
    ull*   zT   = sm + 8192;                  // [64][64]
    float* zTf  = (float*)zT;                 // [64][128]
    ull*   sE2  = sm + 12288;                 // [1024]
    float* sznf = (float*)(sm + 13312);       // [128]
    int*   sidx = (int*)(sm + 13376);         // [128]
    float* sred = (float*)(sm + 13440);       // [8]

    const int tid = threadIdx.x;
    const int w   = tid >> 5;
    const int ln  = tid & 31;
    const int rg  = tid & 15;                 // row group (16) -> pairs rg*4..+3
    const int cg  = tid >> 4;                 // code group (16) -> codes cg*8..+7
    const size_t row0 = (size_t)blockIdx.x * RPB;

    // stage all code norms + chunk 0 (one cp.async group)
    #pragma unroll
    for (int i = 0; i < 2; i++) {
        int u = i * TPB + tid;                // 512 units of 16B = 8KB
        cpa16(&sE2[u * 2], &g_e2d[u * 2]);
    }
    #pragma unroll
    for (int i = 0; i < 16; i++) {
        int u = i * TPB + tid;                // 4096 units: k = u>>6, c2 = u&63
        int k = u >> 6, c2 = u & 63;
        cpa16(&sED[k * 128 + c2 * 2], &g_eTd[k * NE + c2 * 2]);
    }
    CPA_COMMIT();

    // build z tile (transposed, pair-packed) + row norms
    {
        const int row = tid >> 1, h = tid & 1;       // h: k-half 32*h..32*h+31
        const float4* zr = (const float4*)(ze + (row0 + row) * CDIM + h * 32);
        float zn = 0.f;
        #pragma unroll
        for (int q = 0; q < 8; q++) {
            float4 v = zr[q];
            int k = h * 32 + q * 4;
            zTf[(k + 0) * 128 + row] = v.x;
            zTf[(k + 1) * 128 + row] = v.y;
            zTf[(k + 2) * 128 + row] = v.z;
            zTf[(k + 3) * 128 + row] = v.w;
            zn += v.x * v.x + v.y * v.y + v.z * v.z + v.w * v.w;
        }
        zn += __shfl_xor_sync(0xffffffffu, zn, 1);   // combine the two k-halves
        if (h == 0) sznf[row] = zn;
    }
    __syncthreads();

    ull znj[4];
    #pragma unroll
    for (int j = 0; j < 4; j++) znj[j] = ((const ull*)sznf)[rg * 4 + j];

    CPA_WAIT0();
    __syncthreads();                           // sE2 + chunk0 resident

    float best[8]; int bidx[8];
    #pragma unroll
    for (int i = 0; i < 8; i++) { best[i] = 3.4e38f; bidx[i] = 0; }

    const ull  M2 = pk2(-2.f, -2.f);
    const ull* zbase = zT + rg * 4;
    const ull* ebase = sED + cg * 8;

    for (int ch = 0; ch < NCH; ch++) {
        ull acc[4][8];
        #pragma unroll
        for (int j = 0; j < 4; j++)
            #pragma unroll
            for (int c = 0; c < 8; c++) acc[j][c] = 0ull;

        // 32 FFMA2 : 6 LDS.128 per k
        #pragma unroll 8
        for (int k = 0; k < CDIM; k++) {
            const ulonglong2* zk = (const ulonglong2*)(zbase + k * 64);
            const ulonglong2* ek = (const ulonglong2*)(ebase + k * 128);
            ulonglong2 za = zk[0], zb = zk[1];
            ulonglong2 e0 = ek[0], e1 = ek[1], e2v = ek[2], e3 = ek[3];
            ull zr_[4] = { za.x, za.y, zb.x, zb.y };
            ull er_[8] = { e0.x, e0.y, e1.x, e1.y, e2v.x, e2v.y, e3.x, e3.y };
            #pragma unroll
            for (int j = 0; j < 4; j++)
                #pragma unroll
                for (int c = 0; c < 8; c++)
                    acc[j][c] = ffma2(zr_[j], er_[c], acc[j][c]);
        }
        __syncthreads();                       // everyone done reading sED

        if (ch + 1 < NCH) {                    // refill sED with next chunk;
            #pragma unroll                     // copy overlaps the finalize below
            for (int i = 0; i < 16; i++) {
                int u = i * TPB + tid;
                int k = u >> 6, c2 = u & 63;
                cpa16(&sED[k * 128 + c2 * 2],
                      &g_eTd[k * NE + (ch + 1) * CH + c2 * 2]);
            }
            CPA_COMMIT();
        }

        // dist = (||z||^2 + ||e||^2) - 2*dot ; strict < + ascending index
        #pragma unroll
        for (int c = 0; c < 8; c++) {
            ull e2d = sE2[ch * CH + cg * 8 + c];
            int ci  = ch * CH + cg * 8 + c;
            #pragma unroll
            for (int j = 0; j < 4; j++) {
                ull d2 = ffma2(acc[j][c], M2, add2(znj[j], e2d));
                float dlo, dhi; upk2(d2, dlo, dhi);
                if (dlo < best[j * 2])     { best[j * 2]     = dlo; bidx[j * 2]     = ci; }
                if (dhi < best[j * 2 + 1]) { best[j * 2 + 1] = dhi; bidx[j * 2 + 1] = ci; }
            }
        }

        if (ch + 1 < NCH) { CPA_WAIT0(); __syncthreads(); }
    }

    // cross code-group reduction: thread (rg,cg) owns rows rg*8..+7 over its codes
    float* resf = (float*)sED;                 // [16][128]
    int*   resi = (int*)(sED + 1024);          // [16][128]
    __syncthreads();                           // sED safe to reuse
    #pragma unroll
    for (int rl = 0; rl < 8; rl++) {
        int r = rg * 8 + rl;
        resf[cg * 128 + r] = best[rl];
        resi[cg * 128 + r] = bidx[rl];
    }
    __syncthreads();

    if (tid < RPB) {
        float bv = resf[tid]; int bi = resi[tid];
        #pragma unroll
        for (int g = 1; g < 16; g++) {
            float v = resf[g * 128 + tid];
            int  ii = resi[g * 128 + tid];
            if (v < bv || (v == bv && ii < bi)) { bv = v; bi = ii; }
        }
        sidx[tid] = bi;
    }
    __syncthreads();

    // warp-cooperative coalesced output: warp w -> rows w*16..+15
    float ls = 0.f;
    #pragma unroll
    for (int r16 = 0; r16 < 16; r16++) {
        const int row = w * 16 + r16;
        const int code = sidx[row];
        float2 e = ((const float2*)(embs + (size_t)code * CDIM))[ln];
        float2 z = ((const float2*)(ze + (row0 + row) * CDIM))[ln];
        ((float2*)(out + (row0 + row) * CDIM))[ln] = e;
        float d0 = e.x - z.x, d1 = e.y - z.y;
        ls += d0 * d0 + d1 * d1;
    }
    #pragma unroll
    for (int off = 16; off > 0; off >>= 1)
        ls += __shfl_down_sync(0xffffffffu, ls, off);
    if (ln == 0) sred[w] = ls;
    __syncthreads();
    if (tid == 0) {
        float s = 0.f;
        #pragma unroll
        for (int i = 0; i < 8; i++) s += sred[i];
        atomicAdd(&g_loss_acc, (double)s);
    }
}

__global__ void vq_fin(float* loss_out) {
    *loss_out = (float)(1.25 * g_loss_acc / (double)((long long)NROWS * CDIM));
}

extern "C" void kernel_launch(void* const* d_in, const int* in_sizes, int n_in,
                              void* d_out, int out_size) {
    const float* ze   = (const float*)d_in[0];
    const float* embs = (const float*)d_in[1];
    float* out = (float*)d_out;

    cudaFuncSetAttribute(vq_main, cudaFuncAttributeMaxDynamicSharedMemorySize, SMEM_B);

    vq_prep<<<NE * CDIM / 256, 256>>>(embs);
    vq_prep2<<<NE / 128, 128>>>(embs);
    vq_main<<<NBLK, TPB, SMEM_B>>>(ze, embs, out);
    if (out_size > NROWS * CDIM)
        vq_fin<<<1, 1>>>(out + (out_size - 1));
}